// round 16
// baseline (speedup 1.0000x reference)
#include <cuda_runtime.h>
#include <cuda_bf16.h>
#include <cuda_fp16.h>
#include <stdint.h>
#include <math.h>

#define NNODES 50000
#define NEDGES 800000
#define FDIM   128
#define SA     136      // bf16 elements per smem row (272B) -> ldmatrix conflict-free
#define SCANB  256      // scan tile

// ---- scratch (static device memory; no allocations allowed) ----
__device__ __half g_xw[NNODES * FDIM];      // x @ W (fp16, halves gather traffic)
__device__ float g_deg[NNODES];
__device__ float g_dinv[NNODES];
__device__ int   g_counts[NNODES];
__device__ int   g_offsets[NNODES + 1];
__device__ int   g_cursor[NNODES];
__device__ int2  g_csr[NEDGES];             // (src, float-bits of dinv[src]*w)
__device__ int   g_part[256];               // per-block count sums (196 used)
// W^T in bf16 hi/lo split, plain row-major [n][k]
__device__ __nv_bfloat16 g_Whi[FDIM * FDIM];
__device__ __nv_bfloat16 g_Wlo[FDIM * FDIM];

__device__ __forceinline__ uint32_t smem_u32(const void* p) {
    uint32_t a;
    asm("{ .reg .u64 t; cvta.to.shared.u64 t, %1; cvt.u32.u64 %0, t; }" : "=r"(a) : "l"(p));
    return a;
}

// ---------------------------------------------------------------------------
// K1: GRU evolve + write W^T bf16 hi/lo + init deg/counts
// 32 blocks x 512 threads; block handles 4 rows of W0 (cuts Wih/Whh L2 reads 4x)
// ---------------------------------------------------------------------------
__global__ __launch_bounds__(512) void k_evolve(const float* __restrict__ W0,
                         const float* __restrict__ Wih,
                         const float* __restrict__ Whh,
                         const float* __restrict__ bih,
                         const float* __restrict__ bhh) {
    int t = threadIdx.x;
    int i = blockIdx.x * 4 + (t >> 7);   // W0 row
    int j = t & 127;                     // output column

    for (int u = blockIdx.x * 512 + t; u < NNODES; u += 32 * 512) {
        g_deg[u] = 1.0f;      // self-loop weight pre-added
        g_counts[u] = 0;
    }

    __shared__ float w0row[4][FDIM];
    w0row[t >> 7][j] = W0[i * FDIM + j];
    __syncthreads();

    const float4* w0r4 = (const float4*)w0row[t >> 7];
    const float4* Wih4 = (const float4*)Wih;
    const float4* Whh4 = (const float4*)Whh;

    float gir = 0.f, giz = 0.f, gin = 0.f;
    float ghr = 0.f, ghz = 0.f, ghn = 0.f;
#pragma unroll
    for (int k4 = 0; k4 < FDIM / 4; k4++) {
        float4 a = w0r4[k4];
        float4 v;
        v = Wih4[(j)            * 32 + k4]; gir += a.x*v.x + a.y*v.y + a.z*v.z + a.w*v.w;
        v = Wih4[(FDIM + j)     * 32 + k4]; giz += a.x*v.x + a.y*v.y + a.z*v.z + a.w*v.w;
        v = Wih4[(2 * FDIM + j) * 32 + k4]; gin += a.x*v.x + a.y*v.y + a.z*v.z + a.w*v.w;
        v = Whh4[(j)            * 32 + k4]; ghr += a.x*v.x + a.y*v.y + a.z*v.z + a.w*v.w;
        v = Whh4[(FDIM + j)     * 32 + k4]; ghz += a.x*v.x + a.y*v.y + a.z*v.z + a.w*v.w;
        v = Whh4[(2 * FDIM + j) * 32 + k4]; ghn += a.x*v.x + a.y*v.y + a.z*v.z + a.w*v.w;
    }
    gir += bih[j]; giz += bih[FDIM + j]; gin += bih[2 * FDIM + j];
    ghr += bhh[j]; ghz += bhh[FDIM + j]; ghn += bhh[2 * FDIM + j];

    float r = 1.f / (1.f + expf(-(gir + ghr)));
    float z = 1.f / (1.f + expf(-(giz + ghz)));
    float nn = tanhf(gin + r * ghn);
    float Wv = (1.f - z) * nn + z * w0row[t >> 7][j];

    __nv_bfloat16 hb = __float2bfloat16(Wv);
    __nv_bfloat16 lb = __float2bfloat16(Wv - __bfloat162float(hb));
    g_Whi[j * FDIM + i] = hb;
    g_Wlo[j * FDIM + i] = lb;
}

// ---------------------------------------------------------------------------
// K2: degree + in-degree counts over real edges.
// ---------------------------------------------------------------------------
__global__ void k_edge_count(const int* __restrict__ dst,
                             const float* __restrict__ w, int E) {
    int e = blockIdx.x * blockDim.x + threadIdx.x;
    if (e < E) {
        int d = dst[e];
        atomicAdd(&g_deg[d], w[e]);
        atomicAdd(&g_counts[d], 1);
    }
}

// ---------------------------------------------------------------------------
// K3a: per-block reduce of counts -> g_part (+ dinv fused)
// ---------------------------------------------------------------------------
__global__ void k_scan1(int n) {
    int t = threadIdx.x;
    int i = blockIdx.x * SCANB + t;
    int c = 0;
    if (i < n) {
        g_dinv[i] = rsqrtf(g_deg[i]);
        c = g_counts[i];
    }
    __shared__ int ws[8];
    int v = c;
#pragma unroll
    for (int o = 16; o; o >>= 1) v += __shfl_down_sync(0xffffffffu, v, o);
    if ((t & 31) == 0) ws[t >> 5] = v;
    __syncthreads();
    if (t < 8) {
        int s = ws[t];
#pragma unroll
        for (int o = 4; o; o >>= 1) s += __shfl_down_sync(0xffu, s, o);
        if (t == 0) g_part[blockIdx.x] = s;
    }
}

// ---------------------------------------------------------------------------
// K3b: per-block exclusive scan; block base computed in-kernel by reducing
// g_part[0..bid) (196 ints -- cheap), killing the separate middle kernel.
// ---------------------------------------------------------------------------
__global__ void k_scan3(int n) {
    int t = threadIdx.x, lane = t & 31, w = t >> 5;
    int i = blockIdx.x * SCANB + t;

    // base = sum of g_part[0..bid)
    __shared__ int ws[8];
    __shared__ int s_base;
    {
        int pv = (t < blockIdx.x) ? g_part[t] : 0;
        int v = pv;
#pragma unroll
        for (int o = 16; o; o >>= 1) v += __shfl_down_sync(0xffffffffu, v, o);
        if ((t & 31) == 0) ws[t >> 5] = v;
        __syncthreads();
        if (t < 8) {
            int s = ws[t];
#pragma unroll
            for (int o = 4; o; o >>= 1) s += __shfl_down_sync(0xffu, s, o);
            if (t == 0) s_base = s;
        }
        __syncthreads();
    }

    int c = (i < n) ? g_counts[i] : 0;
    int v = c;
#pragma unroll
    for (int o = 1; o < 32; o <<= 1) {
        int u = __shfl_up_sync(0xffffffffu, v, o);
        if (lane >= o) v += u;
    }
    __syncthreads();   // reuse ws safely
    if (lane == 31) ws[w] = v;
    __syncthreads();
    if (t < 8) {
        int s = ws[t];
#pragma unroll
        for (int o = 1; o < 8; o <<= 1) {
            int u = __shfl_up_sync(0xffu, s, o);
            if (t >= o) s += u;
        }
        ws[t] = s;
    }
    __syncthreads();
    int incl = v + (w ? ws[w - 1] : 0);
    int excl = incl - c + s_base;
    if (i < n) {
        g_offsets[i] = excl;
        g_cursor[i]  = excl;
        if (i == n - 1) g_offsets[n] = excl + c;
    }
}

// ---------------------------------------------------------------------------
// K4: scatter edges into CSR-by-dst; packed (src, norm') single 8B store.
// norm' = dinv[src]*w  (dinv[dst] applied in gather)
// ---------------------------------------------------------------------------
__global__ void k_scatter(const int* __restrict__ src,
                          const int* __restrict__ dst,
                          const float* __restrict__ w, int E) {
    int e = blockIdx.x * blockDim.x + threadIdx.x;
    if (e < E) {
        int s = src[e];
        int d = dst[e];
        int pos = atomicAdd(&g_cursor[d], 1);
        g_csr[pos] = make_int2(s, __float_as_int(g_dinv[s] * w[e]));
    }
}

// ---------------------------------------------------------------------------
// K5: xw = x @ W via mma.sync bf16 3-split (hi*hi + hi*lo + lo*hi), fp32 acc.
// Epilogue stores fp16 (half2) into g_xw.
// smem BYTE map: Ahi [0,17408) | Alo [17408,34816) | Bhi [34816,69632) | Blo [69632,104448)
// ---------------------------------------------------------------------------
#define GEMM_SMEM 104448
__global__ __launch_bounds__(256, 2) void k_gemm(const float* __restrict__ x, int n) {
    extern __shared__ __nv_bfloat16 sm[];
    __nv_bfloat16* Ahi = sm;                         // 64 x SA
    __nv_bfloat16* Alo = sm + 64 * SA;
    __nv_bfloat16* Bhi = sm + 2 * 64 * SA;
    __nv_bfloat16* Blo = sm + 2 * 64 * SA + 128 * SA;
    int t = threadIdx.x, lane = t & 31, wid = t >> 5;
    int row0 = blockIdx.x * 64;

    for (int idx = t; idx < 64 * 32; idx += 256) {
        int r = idx >> 5, c4 = idx & 31;
        int gr = row0 + r;
        float4 v = (gr < n) ? ((const float4*)x)[gr * 32 + c4]
                            : make_float4(0.f, 0.f, 0.f, 0.f);
        float f[4] = {v.x, v.y, v.z, v.w};
        uint32_t hp[2], lp[2];
#pragma unroll
        for (int q = 0; q < 2; q++) {
            __nv_bfloat16 h0 = __float2bfloat16(f[2 * q]);
            __nv_bfloat16 h1 = __float2bfloat16(f[2 * q + 1]);
            __nv_bfloat16 l0 = __float2bfloat16(f[2 * q]     - __bfloat162float(h0));
            __nv_bfloat16 l1 = __float2bfloat16(f[2 * q + 1] - __bfloat162float(h1));
            hp[q] = (uint32_t)__bfloat16_as_ushort(h0) | ((uint32_t)__bfloat16_as_ushort(h1) << 16);
            lp[q] = (uint32_t)__bfloat16_as_ushort(l0) | ((uint32_t)__bfloat16_as_ushort(l1) << 16);
        }
        *(uint2*)(Ahi + r * SA + c4 * 4) = make_uint2(hp[0], hp[1]);
        *(uint2*)(Alo + r * SA + c4 * 4) = make_uint2(lp[0], lp[1]);
    }
    for (int idx = t; idx < 128 * 16; idx += 256) {
        int r = idx >> 4, c = idx & 15;
        *(uint4*)(Bhi + r * SA + c * 8) = ((const uint4*)g_Whi)[r * 16 + c];
        *(uint4*)(Blo + r * SA + c * 8) = ((const uint4*)g_Wlo)[r * 16 + c];
    }
    __syncthreads();

    int wr = wid & 3;
    int wc = wid >> 2;
    uint32_t smb = smem_u32(sm);
    uint32_t Abase = smb + (uint32_t)(wr * 16 + (lane & 15)) * 272u + ((uint32_t)(lane >> 4) << 4);
    uint32_t Bbase = smb + 34816u + (uint32_t)(wc * 64 + (lane & 7)) * 272u + ((uint32_t)((lane >> 3) & 1) << 4);

    float c[8][4];
#pragma unroll
    for (int nt = 0; nt < 8; nt++)
#pragma unroll
        for (int q = 0; q < 4; q++) c[nt][q] = 0.f;

#pragma unroll
    for (int pass = 0; pass < 3; pass++) {
        uint32_t Aadd = Abase + (pass == 2 ? 17408u : 0u);   // Alo on pass 2
        uint32_t Badd = Bbase + (pass == 1 ? 34816u : 0u);   // Blo on pass 1 (delta)
#pragma unroll
        for (int kk = 0; kk < 8; kk++) {
            uint32_t a0, a1, a2, a3;
            asm volatile("ldmatrix.sync.aligned.m8n8.x4.shared.b16 {%0,%1,%2,%3}, [%4];"
                         : "=r"(a0), "=r"(a1), "=r"(a2), "=r"(a3)
                         : "r"(Aadd + kk * 32u));
#pragma unroll
            for (int nt = 0; nt < 8; nt++) {
                uint32_t b0, b1;
                asm volatile("ldmatrix.sync.aligned.m8n8.x2.shared.b16 {%0,%1}, [%2];"
                             : "=r"(b0), "=r"(b1)
                             : "r"(Badd + (uint32_t)nt * (8u * 272u) + kk * 32u));
                asm volatile(
                    "mma.sync.aligned.m16n8k16.row.col.f32.bf16.bf16.f32 "
                    "{%0,%1,%2,%3}, {%4,%5,%6,%7}, {%8,%9}, {%0,%1,%2,%3};"
                    : "+f"(c[nt][0]), "+f"(c[nt][1]), "+f"(c[nt][2]), "+f"(c[nt][3])
                    : "r"(a0), "r"(a1), "r"(a2), "r"(a3), "r"(b0), "r"(b1));
            }
        }
    }

    int g  = lane >> 2;
    int cc = (lane & 3) * 2;
    int r0 = row0 + wr * 16 + g;
    int r1 = r0 + 8;
#pragma unroll
    for (int nt = 0; nt < 8; nt++) {
        int col = wc * 64 + nt * 8 + cc;
        if (r0 < n) *(__half2*)(g_xw + r0 * FDIM + col) = __floats2half2_rn(c[nt][0], c[nt][1]);
        if (r1 < n) *(__half2*)(g_xw + r1 * FDIM + col) = __floats2half2_rn(c[nt][2], c[nt][3]);
    }
}

// ---------------------------------------------------------------------------
// K6: warp-per-node gather + tanh + final linear (fused); xw read as fp16.
// h = di * ( sum_e norm'_e * xw[s_e]  +  di * xw[d] )
// ---------------------------------------------------------------------------
__global__ void k_gather(const float* __restrict__ wlin,
                         const float* __restrict__ blin,
                         float* __restrict__ out, int n) {
    int gw   = (blockIdx.x * blockDim.x + threadIdx.x) >> 5;
    int lane = threadIdx.x & 31;
    if (gw >= n) return;

    const uint2* xw2 = (const uint2*)g_xw;   // 4 halves per uint2, 32 per row
    float di = g_dinv[gw];

    uint2 sv = __ldg(&xw2[gw * 32 + lane]);
    float2 s0 = __half22float2(*(const __half2*)&sv.x);
    float2 s1 = __half22float2(*(const __half2*)&sv.y);
    float4 acc = make_float4(di * s0.x, di * s0.y, di * s1.x, di * s1.y);

    int beg = g_offsets[gw];
    int end = g_offsets[gw + 1];
#pragma unroll 4
    for (int e = beg; e < end; e++) {
        int2  ce = __ldg(&g_csr[e]);
        float nm = __int_as_float(ce.y);
        uint2 v  = __ldg(&xw2[ce.x * 32 + lane]);
        float2 v0 = __half22float2(*(const __half2*)&v.x);
        float2 v1 = __half22float2(*(const __half2*)&v.y);
        acc.x += nm * v0.x;
        acc.y += nm * v0.y;
        acc.z += nm * v1.x;
        acc.w += nm * v1.y;
    }
    acc.x *= di; acc.y *= di; acc.z *= di; acc.w *= di;

    float4 wl = ((const float4*)wlin)[lane];
    float p = tanhf(acc.x) * wl.x + tanhf(acc.y) * wl.y +
              tanhf(acc.z) * wl.z + tanhf(acc.w) * wl.w;
#pragma unroll
    for (int o = 16; o; o >>= 1) p += __shfl_down_sync(0xffffffffu, p, o);
    if (lane == 0) out[gw] = p + blin[0];
}

// ---------------------------------------------------------------------------
extern "C" void kernel_launch(void* const* d_in, const int* in_sizes, int n_in,
                              void* d_out, int out_size) {
    const float* x    = (const float*)d_in[0];
    const int*   ei   = (const int*)  d_in[1];
    const float* ew   = (const float*)d_in[2];
    const float* W0   = (const float*)d_in[3];
    const float* Wih  = (const float*)d_in[4];
    const float* Whh  = (const float*)d_in[5];
    const float* bih  = (const float*)d_in[6];
    const float* bhh  = (const float*)d_in[7];
    const float* wlin = (const float*)d_in[8];
    const float* blin = (const float*)d_in[9];
    float* out = (float*)d_out;

    int N = in_sizes[0] / FDIM;
    int E = in_sizes[2];
    const int* src = ei;
    const int* dst = ei + E;
    int nb = (N + SCANB - 1) / SCANB;

    k_evolve<<<32, 512>>>(W0, Wih, Whh, bih, bhh);
    k_edge_count<<<(E + 255) / 256, 256>>>(dst, ew, E);
    k_scan1<<<nb, SCANB>>>(N);
    k_scan3<<<nb, SCANB>>>(N);
    k_scatter<<<(E + 255) / 256, 256>>>(src, dst, ew, E);

    cudaFuncSetAttribute(k_gemm, cudaFuncAttributeMaxDynamicSharedMemorySize, GEMM_SMEM);
    k_gemm<<<(N + 63) / 64, 256, GEMM_SMEM>>>(x, N);

    k_gather<<<(N * 32 + 255) / 256, 256>>>(wlin, blin, out, N);
}

// round 17
// speedup vs baseline: 1.3593x; 1.3593x over previous
#include <cuda_runtime.h>
#include <cuda_bf16.h>
#include <stdint.h>
#include <math.h>

#define NNODES 50000
#define NEDGES 800000
#define FDIM   128
#define SA     136      // bf16 elements per smem row (272B) -> ldmatrix conflict-free
#define SCANB  256      // scan tile
#define DEG_SHIFT 44
#define DEG_SCALE 1048576.0f        // 2^20
#define DEG_INV   (1.0f / 1048576.0f)

// ---- scratch (static device memory; no allocations allowed) ----
__device__ float g_xw[NNODES * FDIM];       // x @ W (fp32)
__device__ unsigned long long g_degcnt[NNODES];  // count<<44 | fixed-point deg sum
__device__ float g_dinv[NNODES];
__device__ int   g_counts[NNODES];
__device__ int   g_offsets[NNODES + 1];
__device__ int   g_cursor[NNODES];
__device__ int2  g_csr[NEDGES];             // (src, float-bits of dinv[src]*w)
__device__ int   g_part[256];               // per-block count sums (196 used)
// W^T in bf16 hi/lo split, plain row-major [n][k]
__device__ __nv_bfloat16 g_Whi[FDIM * FDIM];
__device__ __nv_bfloat16 g_Wlo[FDIM * FDIM];

__device__ __forceinline__ uint32_t smem_u32(const void* p) {
    uint32_t a;
    asm("{ .reg .u64 t; cvta.to.shared.u64 t, %1; cvt.u32.u64 %0, t; }" : "=r"(a) : "l"(p));
    return a;
}

// ---------------------------------------------------------------------------
// K1: GRU evolve + write W^T bf16 hi/lo + init degcnt  (R15 layout: 128x128)
// ---------------------------------------------------------------------------
__global__ void k_evolve(const float* __restrict__ W0,
                         const float* __restrict__ Wih,
                         const float* __restrict__ Whh,
                         const float* __restrict__ bih,
                         const float* __restrict__ bhh) {
    int i = blockIdx.x;
    int j = threadIdx.x;

    for (int u = i * FDIM + j; u < NNODES; u += FDIM * FDIM)
        g_degcnt[u] = 0ull;

    __shared__ float w0row[FDIM];
    w0row[j] = W0[i * FDIM + j];
    __syncthreads();

    const float4* w0r4 = (const float4*)w0row;
    const float4* Wih4 = (const float4*)Wih;
    const float4* Whh4 = (const float4*)Whh;

    float gir = 0.f, giz = 0.f, gin = 0.f;
    float ghr = 0.f, ghz = 0.f, ghn = 0.f;
#pragma unroll
    for (int k4 = 0; k4 < FDIM / 4; k4++) {
        float4 a = w0r4[k4];
        float4 v;
        v = Wih4[(j)            * 32 + k4]; gir += a.x*v.x + a.y*v.y + a.z*v.z + a.w*v.w;
        v = Wih4[(FDIM + j)     * 32 + k4]; giz += a.x*v.x + a.y*v.y + a.z*v.z + a.w*v.w;
        v = Wih4[(2 * FDIM + j) * 32 + k4]; gin += a.x*v.x + a.y*v.y + a.z*v.z + a.w*v.w;
        v = Whh4[(j)            * 32 + k4]; ghr += a.x*v.x + a.y*v.y + a.z*v.z + a.w*v.w;
        v = Whh4[(FDIM + j)     * 32 + k4]; ghz += a.x*v.x + a.y*v.y + a.z*v.z + a.w*v.w;
        v = Whh4[(2 * FDIM + j) * 32 + k4]; ghn += a.x*v.x + a.y*v.y + a.z*v.z + a.w*v.w;
    }
    gir += bih[j]; giz += bih[FDIM + j]; gin += bih[2 * FDIM + j];
    ghr += bhh[j]; ghz += bhh[FDIM + j]; ghn += bhh[2 * FDIM + j];

    float r = 1.f / (1.f + expf(-(gir + ghr)));
    float z = 1.f / (1.f + expf(-(giz + ghz)));
    float nn = tanhf(gin + r * ghn);
    float Wv = (1.f - z) * nn + z * w0row[j];

    __nv_bfloat16 hb = __float2bfloat16(Wv);
    __nv_bfloat16 lb = __float2bfloat16(Wv - __bfloat162float(hb));
    g_Whi[j * FDIM + i] = hb;
    g_Wlo[j * FDIM + i] = lb;
}

// ---------------------------------------------------------------------------
// K2: one packed 64-bit atomic per edge: count in [44:64), fixed-pt deg in [0:44)
// ---------------------------------------------------------------------------
__global__ void k_edge_count(const int* __restrict__ dst,
                             const float* __restrict__ w, int E) {
    int e = blockIdx.x * blockDim.x + threadIdx.x;
    if (e < E) {
        unsigned long long v = (1ull << DEG_SHIFT) |
                               (unsigned long long)(w[e] * DEG_SCALE + 0.5f);
        atomicAdd(&g_degcnt[dst[e]], v);
    }
}

// ---------------------------------------------------------------------------
// K3a: decode degcnt -> dinv + counts; per-block reduce of counts -> g_part
// ---------------------------------------------------------------------------
__global__ void k_scan1(int n) {
    int t = threadIdx.x;
    int i = blockIdx.x * SCANB + t;
    int c = 0;
    if (i < n) {
        unsigned long long v = g_degcnt[i];
        c = (int)(v >> DEG_SHIFT);
        float deg = 1.0f + (float)(v & ((1ull << DEG_SHIFT) - 1ull)) * DEG_INV;
        g_dinv[i]   = rsqrtf(deg);     // deg >= 1 (self loop)
        g_counts[i] = c;
    }
    __shared__ int ws[8];
    int v = c;
#pragma unroll
    for (int o = 16; o; o >>= 1) v += __shfl_down_sync(0xffffffffu, v, o);
    if ((t & 31) == 0) ws[t >> 5] = v;
    __syncthreads();
    if (t < 8) {
        int s = ws[t];
#pragma unroll
        for (int o = 4; o; o >>= 1) s += __shfl_down_sync(0xffu, s, o);
        if (t == 0) g_part[blockIdx.x] = s;
    }
}

// ---------------------------------------------------------------------------
// K3b: per-block exclusive scan; block base reduced in-kernel from g_part.
// ---------------------------------------------------------------------------
__global__ void k_scan3(int n) {
    int t = threadIdx.x, lane = t & 31, w = t >> 5;
    int i = blockIdx.x * SCANB + t;

    __shared__ int ws[8];
    __shared__ int s_base;
    {
        int pv = (t < blockIdx.x) ? g_part[t] : 0;
        int v = pv;
#pragma unroll
        for (int o = 16; o; o >>= 1) v += __shfl_down_sync(0xffffffffu, v, o);
        if ((t & 31) == 0) ws[t >> 5] = v;
        __syncthreads();
        if (t < 8) {
            int s = ws[t];
#pragma unroll
            for (int o = 4; o; o >>= 1) s += __shfl_down_sync(0xffu, s, o);
            if (t == 0) s_base = s;
        }
        __syncthreads();
    }

    int c = (i < n) ? g_counts[i] : 0;
    int v = c;
#pragma unroll
    for (int o = 1; o < 32; o <<= 1) {
        int u = __shfl_up_sync(0xffffffffu, v, o);
        if (lane >= o) v += u;
    }
    __syncthreads();
    if (lane == 31) ws[w] = v;
    __syncthreads();
    if (t < 8) {
        int s = ws[t];
#pragma unroll
        for (int o = 1; o < 8; o <<= 1) {
            int u = __shfl_up_sync(0xffu, s, o);
            if (t >= o) s += u;
        }
        ws[t] = s;
    }
    __syncthreads();
    int incl = v + (w ? ws[w - 1] : 0);
    int excl = incl - c + s_base;
    if (i < n) {
        g_offsets[i] = excl;
        g_cursor[i]  = excl;
        if (i == n - 1) g_offsets[n] = excl + c;
    }
}

// ---------------------------------------------------------------------------
// K4: scatter edges into CSR-by-dst; packed (src, norm') single 8B store.
// norm' = dinv[src]*w  (dinv[dst] applied in gather)
// ---------------------------------------------------------------------------
__global__ void k_scatter(const int* __restrict__ src,
                          const int* __restrict__ dst,
                          const float* __restrict__ w, int E) {
    int e = blockIdx.x * blockDim.x + threadIdx.x;
    if (e < E) {
        int s = src[e];
        int d = dst[e];
        int pos = atomicAdd(&g_cursor[d], 1);
        g_csr[pos] = make_int2(s, __float_as_int(g_dinv[s] * w[e]));
    }
}

// ---------------------------------------------------------------------------
// K5: xw = x @ W via mma.sync bf16 3-split (hi*hi + hi*lo + lo*hi), fp32 acc.
// smem BYTE map: Ahi [0,17408) | Alo [17408,34816) | Bhi [34816,69632) | Blo [69632,104448)
// ---------------------------------------------------------------------------
#define GEMM_SMEM 104448
__global__ __launch_bounds__(256, 2) void k_gemm(const float* __restrict__ x, int n) {
    extern __shared__ __nv_bfloat16 sm[];
    __nv_bfloat16* Ahi = sm;                         // 64 x SA
    __nv_bfloat16* Alo = sm + 64 * SA;
    __nv_bfloat16* Bhi = sm + 2 * 64 * SA;
    __nv_bfloat16* Blo = sm + 2 * 64 * SA + 128 * SA;
    int t = threadIdx.x, lane = t & 31, wid = t >> 5;
    int row0 = blockIdx.x * 64;

    for (int idx = t; idx < 64 * 32; idx += 256) {
        int r = idx >> 5, c4 = idx & 31;
        int gr = row0 + r;
        float4 v = (gr < n) ? ((const float4*)x)[gr * 32 + c4]
                            : make_float4(0.f, 0.f, 0.f, 0.f);
        float f[4] = {v.x, v.y, v.z, v.w};
        uint32_t hp[2], lp[2];
#pragma unroll
        for (int q = 0; q < 2; q++) {
            __nv_bfloat16 h0 = __float2bfloat16(f[2 * q]);
            __nv_bfloat16 h1 = __float2bfloat16(f[2 * q + 1]);
            __nv_bfloat16 l0 = __float2bfloat16(f[2 * q]     - __bfloat162float(h0));
            __nv_bfloat16 l1 = __float2bfloat16(f[2 * q + 1] - __bfloat162float(h1));
            hp[q] = (uint32_t)__bfloat16_as_ushort(h0) | ((uint32_t)__bfloat16_as_ushort(h1) << 16);
            lp[q] = (uint32_t)__bfloat16_as_ushort(l0) | ((uint32_t)__bfloat16_as_ushort(l1) << 16);
        }
        *(uint2*)(Ahi + r * SA + c4 * 4) = make_uint2(hp[0], hp[1]);
        *(uint2*)(Alo + r * SA + c4 * 4) = make_uint2(lp[0], lp[1]);
    }
    for (int idx = t; idx < 128 * 16; idx += 256) {
        int r = idx >> 4, c = idx & 15;
        *(uint4*)(Bhi + r * SA + c * 8) = ((const uint4*)g_Whi)[r * 16 + c];
        *(uint4*)(Blo + r * SA + c * 8) = ((const uint4*)g_Wlo)[r * 16 + c];
    }
    __syncthreads();

    int wr = wid & 3;
    int wc = wid >> 2;
    uint32_t smb = smem_u32(sm);
    uint32_t Abase = smb + (uint32_t)(wr * 16 + (lane & 15)) * 272u + ((uint32_t)(lane >> 4) << 4);
    uint32_t Bbase = smb + 34816u + (uint32_t)(wc * 64 + (lane & 7)) * 272u + ((uint32_t)((lane >> 3) & 1) << 4);

    float c[8][4];
#pragma unroll
    for (int nt = 0; nt < 8; nt++)
#pragma unroll
        for (int q = 0; q < 4; q++) c[nt][q] = 0.f;

#pragma unroll
    for (int pass = 0; pass < 3; pass++) {
        uint32_t Aadd = Abase + (pass == 2 ? 17408u : 0u);   // Alo on pass 2
        uint32_t Badd = Bbase + (pass == 1 ? 34816u : 0u);   // Blo on pass 1 (delta)
#pragma unroll
        for (int kk = 0; kk < 8; kk++) {
            uint32_t a0, a1, a2, a3;
            asm volatile("ldmatrix.sync.aligned.m8n8.x4.shared.b16 {%0,%1,%2,%3}, [%4];"
                         : "=r"(a0), "=r"(a1), "=r"(a2), "=r"(a3)
                         : "r"(Aadd + kk * 32u));
#pragma unroll
            for (int nt = 0; nt < 8; nt++) {
                uint32_t b0, b1;
                asm volatile("ldmatrix.sync.aligned.m8n8.x2.shared.b16 {%0,%1}, [%2];"
                             : "=r"(b0), "=r"(b1)
                             : "r"(Badd + (uint32_t)nt * (8u * 272u) + kk * 32u));
                asm volatile(
                    "mma.sync.aligned.m16n8k16.row.col.f32.bf16.bf16.f32 "
                    "{%0,%1,%2,%3}, {%4,%5,%6,%7}, {%8,%9}, {%0,%1,%2,%3};"
                    : "+f"(c[nt][0]), "+f"(c[nt][1]), "+f"(c[nt][2]), "+f"(c[nt][3])
                    : "r"(a0), "r"(a1), "r"(a2), "r"(a3), "r"(b0), "r"(b1));
            }
        }
    }

    int g  = lane >> 2;
    int cc = (lane & 3) * 2;
    int r0 = row0 + wr * 16 + g;
    int r1 = r0 + 8;
#pragma unroll
    for (int nt = 0; nt < 8; nt++) {
        int col = wc * 64 + nt * 8 + cc;
        if (r0 < n) *(float2*)(g_xw + r0 * FDIM + col) = make_float2(c[nt][0], c[nt][1]);
        if (r1 < n) *(float2*)(g_xw + r1 * FDIM + col) = make_float2(c[nt][2], c[nt][3]);
    }
}

// ---------------------------------------------------------------------------
// K6: warp-per-node gather + tanh + final linear (fused); fp32 float4 path.
// h = di * ( sum_e norm'_e * xw[s_e]  +  di * xw[d] )
// ---------------------------------------------------------------------------
__global__ void k_gather(const float* __restrict__ wlin,
                         const float* __restrict__ blin,
                         float* __restrict__ out, int n) {
    int gw   = (blockIdx.x * blockDim.x + threadIdx.x) >> 5;
    int lane = threadIdx.x & 31;
    if (gw >= n) return;

    const float4* xw4 = (const float4*)g_xw;
    float di = g_dinv[gw];
    float4 self = xw4[gw * 32 + lane];
    float4 acc;
    acc.x = di * self.x; acc.y = di * self.y;
    acc.z = di * self.z; acc.w = di * self.w;

    int beg = g_offsets[gw];
    int end = g_offsets[gw + 1];
#pragma unroll 4
    for (int e = beg; e < end; e++) {
        int2  ce = __ldg(&g_csr[e]);
        float nm = __int_as_float(ce.y);
        float4 v = xw4[ce.x * 32 + lane];
        acc.x += nm * v.x;
        acc.y += nm * v.y;
        acc.z += nm * v.z;
        acc.w += nm * v.w;
    }
    acc.x *= di; acc.y *= di; acc.z *= di; acc.w *= di;

    float4 wl = ((const float4*)wlin)[lane];
    float p = tanhf(acc.x) * wl.x + tanhf(acc.y) * wl.y +
              tanhf(acc.z) * wl.z + tanhf(acc.w) * wl.w;
#pragma unroll
    for (int o = 16; o; o >>= 1) p += __shfl_down_sync(0xffffffffu, p, o);
    if (lane == 0) out[gw] = p + blin[0];
}

// ---------------------------------------------------------------------------
extern "C" void kernel_launch(void* const* d_in, const int* in_sizes, int n_in,
                              void* d_out, int out_size) {
    const float* x    = (const float*)d_in[0];
    const int*   ei   = (const int*)  d_in[1];
    const float* ew   = (const float*)d_in[2];
    const float* W0   = (const float*)d_in[3];
    const float* Wih  = (const float*)d_in[4];
    const float* Whh  = (const float*)d_in[5];
    const float* bih  = (const float*)d_in[6];
    const float* bhh  = (const float*)d_in[7];
    const float* wlin = (const float*)d_in[8];
    const float* blin = (const float*)d_in[9];
    float* out = (float*)d_out;

    int N = in_sizes[0] / FDIM;
    int E = in_sizes[2];
    const int* src = ei;
    const int* dst = ei + E;
    int nb = (N + SCANB - 1) / SCANB;

    k_evolve<<<FDIM, FDIM>>>(W0, Wih, Whh, bih, bhh);
    k_edge_count<<<(E + 255) / 256, 256>>>(dst, ew, E);
    k_scan1<<<nb, SCANB>>>(N);
    k_scan3<<<nb, SCANB>>>(N);
    k_scatter<<<(E + 255) / 256, 256>>>(src, dst, ew, E);

    cudaFuncSetAttribute(k_gemm, cudaFuncAttributeMaxDynamicSharedMemorySize, GEMM_SMEM);
    k_gemm<<<(N + 63) / 64, 256, GEMM_SMEM>>>(x, N);

    k_gather<<<(N * 32 + 255) / 256, 256>>>(wlin, blin, out, N);
}